// round 1
// baseline (speedup 1.0000x reference)
#include <cuda_runtime.h>
#include <math.h>
#include <stdint.h>

#define N_TOK 4096
#define DMODEL 1024

// Scratch (device globals; no allocation allowed in kernel_launch)
__device__ float g_q[(size_t)N_TOK * DMODEL];
__device__ float g_k[(size_t)N_TOK * DMODEL];
__device__ float g_v[(size_t)N_TOK * DMODEL];
__device__ float g_s[(size_t)N_TOK * N_TOK];
__device__ float g_rowsum[N_TOK];

// ---------------------------------------------------------------------------
// C[M,Ncols] = alpha * A[M,K] @ B[Ncols,K]^T   (both row-major, K contiguous)
// 128x128 tile, BK=8, 256 threads, 8x8 per thread.
// ---------------------------------------------------------------------------
__global__ __launch_bounds__(256) void gemm_nt(
    const float* __restrict__ A, const float* __restrict__ B,
    float* __restrict__ C, int M, int Ncols, int K, float alpha)
{
    __shared__ float As[8][128];
    __shared__ float Bs[8][128];

    const int tid = threadIdx.x;
    const int tx = tid & 15;        // 16 thread-cols
    const int ty = tid >> 4;        // 16 thread-rows

    const float* Ab = A + (size_t)blockIdx.y * 128 * K;
    const float* Bb = B + (size_t)blockIdx.x * 128 * K;

    float acc[8][8];
#pragma unroll
    for (int m = 0; m < 8; m++)
#pragma unroll
        for (int n = 0; n < 8; n++) acc[m][n] = 0.0f;

    const int lrow = tid >> 1;          // 0..127
    const int lcol = (tid & 1) * 4;     // 0 or 4

    for (int k0 = 0; k0 < K; k0 += 8) {
        float4 a = *reinterpret_cast<const float4*>(Ab + (size_t)lrow * K + k0 + lcol);
        float4 b = *reinterpret_cast<const float4*>(Bb + (size_t)lrow * K + k0 + lcol);
        As[lcol + 0][lrow] = a.x; As[lcol + 1][lrow] = a.y;
        As[lcol + 2][lrow] = a.z; As[lcol + 3][lrow] = a.w;
        Bs[lcol + 0][lrow] = b.x; Bs[lcol + 1][lrow] = b.y;
        Bs[lcol + 2][lrow] = b.z; Bs[lcol + 3][lrow] = b.w;
        __syncthreads();

#pragma unroll
        for (int kk = 0; kk < 8; kk++) {
            float ar[8], br[8];
#pragma unroll
            for (int m = 0; m < 8; m++) ar[m] = As[kk][ty * 8 + m];
#pragma unroll
            for (int n = 0; n < 8; n++) br[n] = Bs[kk][tx * 8 + n];
#pragma unroll
            for (int m = 0; m < 8; m++)
#pragma unroll
                for (int n = 0; n < 8; n++)
                    acc[m][n] = fmaf(ar[m], br[n], acc[m][n]);
        }
        __syncthreads();
    }

#pragma unroll
    for (int m = 0; m < 8; m++) {
        size_t row = (size_t)blockIdx.y * 128 + ty * 8 + m;
        float* Crow = C + row * Ncols + blockIdx.x * 128 + tx * 8;
#pragma unroll
        for (int n = 0; n < 8; n += 4) {
            float4 o;
            o.x = acc[m][n + 0] * alpha;
            o.y = acc[m][n + 1] * alpha;
            o.z = acc[m][n + 2] * alpha;
            o.w = acc[m][n + 3] * alpha;
            *reinterpret_cast<float4*>(Crow + n) = o;
        }
    }
}

// ---------------------------------------------------------------------------
// C[M,Ncols] = (A[M,K] @ B[K,Ncols]) * (1/rowsum[row])   (all row-major)
// ---------------------------------------------------------------------------
__global__ __launch_bounds__(256) void gemm_nn_scaled(
    const float* __restrict__ A, const float* __restrict__ B,
    const float* __restrict__ rowsum,
    float* __restrict__ C, int M, int Ncols, int K)
{
    __shared__ float As[8][128];
    __shared__ float Bs[8][128];

    const int tid = threadIdx.x;
    const int tx = tid & 15;
    const int ty = tid >> 4;

    const float* Ab = A + (size_t)blockIdx.y * 128 * K;

    float acc[8][8];
#pragma unroll
    for (int m = 0; m < 8; m++)
#pragma unroll
        for (int n = 0; n < 8; n++) acc[m][n] = 0.0f;

    const int lrowA = tid >> 1;
    const int lcolA = (tid & 1) * 4;
    const int lrowB = tid >> 5;          // 0..7  (k within tile)
    const int lcolB = (tid & 31) * 4;    // 0..124

    for (int k0 = 0; k0 < K; k0 += 8) {
        float4 a = *reinterpret_cast<const float4*>(Ab + (size_t)lrowA * K + k0 + lcolA);
        As[lcolA + 0][lrowA] = a.x; As[lcolA + 1][lrowA] = a.y;
        As[lcolA + 2][lrowA] = a.z; As[lcolA + 3][lrowA] = a.w;
        float4 b = *reinterpret_cast<const float4*>(
            B + (size_t)(k0 + lrowB) * Ncols + blockIdx.x * 128 + lcolB);
        *reinterpret_cast<float4*>(&Bs[lrowB][lcolB]) = b;
        __syncthreads();

#pragma unroll
        for (int kk = 0; kk < 8; kk++) {
            float ar[8], br[8];
#pragma unroll
            for (int m = 0; m < 8; m++) ar[m] = As[kk][ty * 8 + m];
#pragma unroll
            for (int n = 0; n < 8; n++) br[n] = Bs[kk][tx * 8 + n];
#pragma unroll
            for (int m = 0; m < 8; m++)
#pragma unroll
                for (int n = 0; n < 8; n++)
                    acc[m][n] = fmaf(ar[m], br[n], acc[m][n]);
        }
        __syncthreads();
    }

#pragma unroll
    for (int m = 0; m < 8; m++) {
        size_t row = (size_t)blockIdx.y * 128 + ty * 8 + m;
        float rinv = 1.0f / rowsum[row];
        float* Crow = C + row * Ncols + blockIdx.x * 128 + tx * 8;
#pragma unroll
        for (int n = 0; n < 8; n += 4) {
            float4 o;
            o.x = acc[m][n + 0] * rinv;
            o.y = acc[m][n + 1] * rinv;
            o.z = acc[m][n + 2] * rinv;
            o.w = acc[m][n + 3] * rinv;
            *reinterpret_cast<float4*>(Crow + n) = o;
        }
    }
}

// ---------------------------------------------------------------------------
// Row softmax (unnormalized): s[i] <- exp(s[i]-max); rowsum[row] = sum
// One block per row, 256 threads.
// ---------------------------------------------------------------------------
__global__ __launch_bounds__(256) void softmax_rows(
    float* __restrict__ S, float* __restrict__ rowsum)
{
    __shared__ float red[256];
    const int row = blockIdx.x;
    const int tid = threadIdx.x;
    float* s = S + (size_t)row * N_TOK;

    float m = -INFINITY;
    for (int i = tid * 4; i < N_TOK; i += 256 * 4) {
        float4 v4 = *reinterpret_cast<const float4*>(s + i);
        m = fmaxf(m, fmaxf(fmaxf(v4.x, v4.y), fmaxf(v4.z, v4.w)));
    }
    red[tid] = m; __syncthreads();
    for (int o = 128; o > 0; o >>= 1) {
        if (tid < o) red[tid] = fmaxf(red[tid], red[tid + o]);
        __syncthreads();
    }
    m = red[0]; __syncthreads();

    float sum = 0.0f;
    for (int i = tid * 4; i < N_TOK; i += 256 * 4) {
        float4 v4 = *reinterpret_cast<float4*>(s + i);
        v4.x = __expf(v4.x - m); v4.y = __expf(v4.y - m);
        v4.z = __expf(v4.z - m); v4.w = __expf(v4.w - m);
        sum += v4.x + v4.y + v4.z + v4.w;
        *reinterpret_cast<float4*>(s + i) = v4;
    }
    red[tid] = sum; __syncthreads();
    for (int o = 128; o > 0; o >>= 1) {
        if (tid < o) red[tid] += red[tid + o];
        __syncthreads();
    }
    if (tid == 0) rowsum[row] = red[0];
}

// ---------------------------------------------------------------------------
extern "C" void kernel_launch(void* const* d_in, const int* in_sizes, int n_in,
                              void* d_out, int out_size)
{
    const float* x  = (const float*)d_in[0];
    const float* wq = (const float*)d_in[1];
    const float* wk = (const float*)d_in[2];
    const float* wv = (const float*)d_in[3];
    float* out = (float*)d_out;

    float *q, *k, *v, *s, *rs;
    cudaGetSymbolAddress((void**)&q,  g_q);
    cudaGetSymbolAddress((void**)&k,  g_k);
    cudaGetSymbolAddress((void**)&v,  g_v);
    cudaGetSymbolAddress((void**)&s,  g_s);
    cudaGetSymbolAddress((void**)&rs, g_rowsum);

    dim3 blk(256);
    dim3 grid_qkv(DMODEL / 128, N_TOK / 128);   // (8, 32)
    dim3 grid_sc(N_TOK / 128, N_TOK / 128);     // (32, 32)

    // Projections: q = x @ wq^T etc.
    gemm_nt<<<grid_qkv, blk>>>(x, wq, q, N_TOK, DMODEL, DMODEL, 1.0f);
    gemm_nt<<<grid_qkv, blk>>>(x, wk, k, N_TOK, DMODEL, DMODEL, 1.0f);
    gemm_nt<<<grid_qkv, blk>>>(x, wv, v, N_TOK, DMODEL, DMODEL, 1.0f);

    // scores = (q @ k^T) / sqrt(1024)
    gemm_nt<<<grid_sc, blk>>>(q, k, s, N_TOK, N_TOK, DMODEL, 1.0f / 32.0f);

    // in-place exp(s - rowmax), rowsum
    softmax_rows<<<N_TOK, blk>>>(s, rs);

    // out = (P @ v) / rowsum
    gemm_nn_scaled<<<grid_qkv, blk>>>(s, v, rs, out, N_TOK, DMODEL, N_TOK);
}

// round 3
// speedup vs baseline: 2.7498x; 2.7498x over previous
#include <cuda_runtime.h>
#include <cuda_bf16.h>
#include <math.h>
#include <stdint.h>

#define N_TOK 4096
#define DMODEL 1024

// ---------------------------------------------------------------------------
// Scratch (device globals)
// ---------------------------------------------------------------------------
__device__ __nv_bfloat16 g_x3[(size_t)N_TOK * 3 * DMODEL];          // [4096, 3072]
__device__ __nv_bfloat16 g_w3[(size_t)3 * DMODEL * 3 * DMODEL];     // [3072, 3072]
__device__ float         g_qkv[(size_t)N_TOK * 3 * DMODEL];         // [4096, 3072]
__device__ __nv_bfloat16 g_q3[(size_t)N_TOK * 3 * DMODEL];          // [4096, 3072]
__device__ __nv_bfloat16 g_k3[(size_t)N_TOK * 3 * DMODEL];          // [4096, 3072]
__device__ float         g_s[(size_t)N_TOK * N_TOK];                // [4096, 4096]
__device__ __nv_bfloat16 g_p3[(size_t)N_TOK * 3 * N_TOK];           // [4096, 12288]
__device__ __nv_bfloat16 g_v3t[(size_t)DMODEL * 3 * N_TOK];         // [1024, 12288]
__device__ float         g_rowsum[N_TOK];

// ---------------------------------------------------------------------------
// PTX helpers (baseline sm_80+ instructions only — no 'a'-gated features)
// ---------------------------------------------------------------------------
__device__ __forceinline__ uint32_t smem_u32(const void* p) {
    uint32_t a;
    asm("{ .reg .u64 t; cvta.to.shared.u64 t, %1; cvt.u32.u64 %0, t; }" : "=r"(a) : "l"(p));
    return a;
}
__device__ __forceinline__ void cp_async16(uint32_t saddr, const void* gptr) {
    asm volatile("cp.async.cg.shared.global [%0], [%1], 16;" :: "r"(saddr), "l"(gptr) : "memory");
}
__device__ __forceinline__ void cp_commit() {
    asm volatile("cp.async.commit_group;" ::: "memory");
}
__device__ __forceinline__ void cp_wait1() {
    asm volatile("cp.async.wait_group 1;" ::: "memory");
}
__device__ __forceinline__ void ldsm_x4(uint32_t& r0, uint32_t& r1, uint32_t& r2, uint32_t& r3,
                                        uint32_t addr) {
    asm volatile("ldmatrix.sync.aligned.m8n8.x4.shared.b16 {%0,%1,%2,%3}, [%4];"
                 : "=r"(r0), "=r"(r1), "=r"(r2), "=r"(r3) : "r"(addr));
}
__device__ __forceinline__ void mma_bf16(float& c0, float& c1, float& c2, float& c3,
                                         uint32_t a0, uint32_t a1, uint32_t a2, uint32_t a3,
                                         uint32_t b0, uint32_t b1) {
    asm volatile(
        "mma.sync.aligned.m16n8k16.row.col.f32.bf16.bf16.f32 "
        "{%0,%1,%2,%3}, {%4,%5,%6,%7}, {%8,%9}, {%0,%1,%2,%3};"
        : "+f"(c0), "+f"(c1), "+f"(c2), "+f"(c3)
        : "r"(a0), "r"(a1), "r"(a2), "r"(a3), "r"(b0), "r"(b1));
}
#define SW128(b) ((b) ^ (((b) >> 3) & 0x70))

// ---------------------------------------------------------------------------
// bf16 tensor-core GEMM (NT): C[M,N] = scale * A[M,Kb] @ B[N,Kb]^T
// Both operands row-major with contiguous Kb. CTA tile 128x128, BK=64,
// 3-stage cp.async pipeline, 8 warps (2x4), warp tile 64x32.
// scale = alpha, or 1/rowsum[row] when rowsum != nullptr.
// ---------------------------------------------------------------------------
#define STAGES 3
#define STAGE_BYTES 32768            // A 16KB + B 16KB
#define GEMM_SMEM_BYTES (STAGES * STAGE_BYTES)

__global__ __launch_bounds__(256)
void gemm_bf16_tc(const __nv_bfloat16* __restrict__ A,
                  const __nv_bfloat16* __restrict__ B,
                  float* __restrict__ C, int Kb, int ldc, float alpha,
                  const float* __restrict__ rowsum)
{
    extern __shared__ char smem[];
    const uint32_t sbase = smem_u32(smem);

    const int tid  = threadIdx.x;
    const int wid  = tid >> 5;
    const int lane = tid & 31;
    const int warp_m = wid >> 2;    // 0..1  (64-row slab)
    const int warp_n = wid & 3;     // 0..3  (32-col slab)

    const int m0 = blockIdx.y * 128;
    const int n0 = blockIdx.x * 128;
    const int T  = Kb >> 6;

    // global load addressing: thread t loads 4 chunks of 16B per tile per matrix
    // chunk id = tid + j*256 ; row = chunk>>3 (0..127), col16 = chunk&7
    const __nv_bfloat16* Ab = A + (size_t)m0 * Kb;
    const __nv_bfloat16* Bb = B + (size_t)n0 * Kb;

    // ldmatrix row/chunk components (loop-invariant pieces)
    const uint32_t a_row = (uint32_t)(warp_m * 64 + (lane & 15)) * 128;
    const uint32_t a_chk = (uint32_t)(lane >> 4) * 16;
    const uint32_t b_row = (uint32_t)(warp_n * 32 + (lane & 7) + ((lane >> 4) & 1) * 8) * 128;
    const uint32_t b_chk = (uint32_t)((lane >> 3) & 1) * 16;

    float acc[4][4][4];
#pragma unroll
    for (int mi = 0; mi < 4; mi++)
#pragma unroll
        for (int ni = 0; ni < 4; ni++)
#pragma unroll
            for (int e = 0; e < 4; e++) acc[mi][ni][e] = 0.0f;

    // -------- prologue: issue stages 0 and 1 --------
#pragma unroll
    for (int p = 0; p < 2; p++) {
        const uint32_t sa = sbase + p * STAGE_BYTES;
        const uint32_t sb = sa + 16384;
        const int k0 = p << 6;
#pragma unroll
        for (int j = 0; j < 4; j++) {
            int chunk = tid + j * 256;
            int r = chunk >> 3, c16 = chunk & 7;
            cp_async16(sa + SW128((uint32_t)(r * 128 + c16 * 16)),
                       Ab + (size_t)r * Kb + k0 + c16 * 8);
        }
#pragma unroll
        for (int j = 0; j < 4; j++) {
            int chunk = tid + j * 256;
            int r = chunk >> 3, c16 = chunk & 7;
            cp_async16(sb + SW128((uint32_t)(r * 128 + c16 * 16)),
                       Bb + (size_t)r * Kb + k0 + c16 * 8);
        }
        cp_commit();
    }

    // -------- mainloop --------
    for (int i = 0; i < T; i++) {
        cp_wait1();
        __syncthreads();

        // issue tile i+2 into stage (i+2)%3 (overlaps with compute below)
        if (i + 2 < T) {
            const int s2 = (i + 2) % STAGES;
            const uint32_t sa = sbase + s2 * STAGE_BYTES;
            const uint32_t sb = sa + 16384;
            const int k0 = (i + 2) << 6;
#pragma unroll
            for (int j = 0; j < 4; j++) {
                int chunk = tid + j * 256;
                int r = chunk >> 3, c16 = chunk & 7;
                cp_async16(sa + SW128((uint32_t)(r * 128 + c16 * 16)),
                           Ab + (size_t)r * Kb + k0 + c16 * 8);
            }
#pragma unroll
            for (int j = 0; j < 4; j++) {
                int chunk = tid + j * 256;
                int r = chunk >> 3, c16 = chunk & 7;
                cp_async16(sb + SW128((uint32_t)(r * 128 + c16 * 16)),
                           Bb + (size_t)r * Kb + k0 + c16 * 8);
            }
        }
        cp_commit();

        // compute tile i from stage i%3
        const uint32_t sa = sbase + (i % STAGES) * STAGE_BYTES;
        const uint32_t sb = sa + 16384;
#pragma unroll
        for (int kk = 0; kk < 4; kk++) {
            uint32_t a[4][4];   // [mi][reg]
            uint32_t b[4][2];   // [ni][reg]
#pragma unroll
            for (int mi = 0; mi < 4; mi++) {
                uint32_t addr = sa + SW128(a_row + (uint32_t)(mi * 16 * 128) +
                                           (uint32_t)(kk * 32) + a_chk);
                ldsm_x4(a[mi][0], a[mi][1], a[mi][2], a[mi][3], addr);
            }
#pragma unroll
            for (int np = 0; np < 2; np++) {   // n-frag pairs (n16 per x4)
                uint32_t addr = sb + SW128(b_row + (uint32_t)(np * 16 * 128) +
                                           (uint32_t)(kk * 32) + b_chk);
                uint32_t r0, r1, r2, r3;
                ldsm_x4(r0, r1, r2, r3, addr);
                b[np * 2 + 0][0] = r0; b[np * 2 + 0][1] = r1;
                b[np * 2 + 1][0] = r2; b[np * 2 + 1][1] = r3;
            }
#pragma unroll
            for (int mi = 0; mi < 4; mi++)
#pragma unroll
                for (int ni = 0; ni < 4; ni++)
                    mma_bf16(acc[mi][ni][0], acc[mi][ni][1], acc[mi][ni][2], acc[mi][ni][3],
                             a[mi][0], a[mi][1], a[mi][2], a[mi][3],
                             b[ni][0], b[ni][1]);
        }
        __syncthreads();
    }

    // -------- epilogue --------
    const int col_base = n0 + warp_n * 32 + (lane & 3) * 2;
    const int row_base = m0 + warp_m * 64 + (lane >> 2);
#pragma unroll
    for (int mi = 0; mi < 4; mi++) {
        const int r0 = row_base + mi * 16;
        const int r1 = r0 + 8;
        float sc0, sc1;
        if (rowsum) { sc0 = 1.0f / rowsum[r0]; sc1 = 1.0f / rowsum[r1]; }
        else        { sc0 = alpha; sc1 = alpha; }
        float* C0 = C + (size_t)r0 * ldc;
        float* C1 = C + (size_t)r1 * ldc;
#pragma unroll
        for (int ni = 0; ni < 4; ni++) {
            const int c = col_base + ni * 8;
            float2 v0 = make_float2(acc[mi][ni][0] * sc0, acc[mi][ni][1] * sc0);
            float2 v1 = make_float2(acc[mi][ni][2] * sc1, acc[mi][ni][3] * sc1);
            *reinterpret_cast<float2*>(C0 + c) = v0;
            *reinterpret_cast<float2*>(C1 + c) = v1;
        }
    }
}

// ---------------------------------------------------------------------------
// Split-convert: in fp32 [R, C] (leading dim ld) -> out bf16 [R, 3C]
// patB==0: [hi | hi | lo]   (A operand)
// patB==1: [hi | lo | hi]   (B operand)
// ---------------------------------------------------------------------------
__global__ __launch_bounds__(256) void convert_split(
    const float* __restrict__ in, int ld, int R, int C,
    __nv_bfloat16* __restrict__ out, int patB)
{
    size_t idx = ((size_t)blockIdx.x * 256 + threadIdx.x) * 4;
    size_t total = (size_t)R * C;
    if (idx >= total) return;
    int r = (int)(idx / C);
    int c = (int)(idx % C);
    float4 v = *reinterpret_cast<const float4*>(in + (size_t)r * ld + c);
    float vv[4] = {v.x, v.y, v.z, v.w};
    __nv_bfloat16 hi[4], lo[4];
#pragma unroll
    for (int i = 0; i < 4; i++) {
        hi[i] = __float2bfloat16(vv[i]);
        lo[i] = __float2bfloat16(vv[i] - __bfloat162float(hi[i]));
    }
    size_t ob = (size_t)r * 3 * C + c;
    __nv_bfloat16* o0 = out + ob;
    __nv_bfloat16* o1 = out + ob + C;
    __nv_bfloat16* o2 = out + ob + 2 * C;
#pragma unroll
    for (int i = 0; i < 4; i++) {
        o0[i] = hi[i];
        o1[i] = patB ? lo[i] : hi[i];
        o2[i] = patB ? hi[i] : lo[i];
    }
}

// ---------------------------------------------------------------------------
// Transpose + split-convert for V: in fp32 [4096(K), 1024(N)] (ld given) ->
// out bf16 [1024, 12288] = [vh | vl | vh] along cols.
// ---------------------------------------------------------------------------
__global__ __launch_bounds__(256) void transpose_split_v(
    const float* __restrict__ in, int ld, __nv_bfloat16* __restrict__ out)
{
    __shared__ float tile[32][33];
    int n0 = blockIdx.x * 32;
    int k0 = blockIdx.y * 32;
    int tx = threadIdx.x & 31;
    int ty = threadIdx.x >> 5;
#pragma unroll
    for (int l = 0; l < 4; l++)
        tile[ty + 8 * l][tx] = in[(size_t)(k0 + ty + 8 * l) * ld + n0 + tx];
    __syncthreads();
#pragma unroll
    for (int l = 0; l < 4; l++) {
        int n = n0 + ty + 8 * l;
        float v = tile[tx][ty + 8 * l];
        __nv_bfloat16 hi = __float2bfloat16(v);
        __nv_bfloat16 lo = __float2bfloat16(v - __bfloat162float(hi));
        size_t ob = (size_t)n * (3 * N_TOK) + k0 + tx;
        out[ob] = hi;
        out[ob + N_TOK] = lo;
        out[ob + 2 * N_TOK] = hi;
    }
}

// ---------------------------------------------------------------------------
// Row softmax (unnormalized): s[i] <- exp(s[i]-max); rowsum[row] = sum
// ---------------------------------------------------------------------------
__global__ __launch_bounds__(256) void softmax_rows(
    float* __restrict__ S, float* __restrict__ rowsum)
{
    __shared__ float red[256];
    const int row = blockIdx.x;
    const int tid = threadIdx.x;
    float* s = S + (size_t)row * N_TOK;

    float m = -INFINITY;
    for (int i = tid * 4; i < N_TOK; i += 256 * 4) {
        float4 v4 = *reinterpret_cast<const float4*>(s + i);
        m = fmaxf(m, fmaxf(fmaxf(v4.x, v4.y), fmaxf(v4.z, v4.w)));
    }
    red[tid] = m; __syncthreads();
    for (int o = 128; o > 0; o >>= 1) {
        if (tid < o) red[tid] = fmaxf(red[tid], red[tid + o]);
        __syncthreads();
    }
    m = red[0]; __syncthreads();

    float sum = 0.0f;
    for (int i = tid * 4; i < N_TOK; i += 256 * 4) {
        float4 v4 = *reinterpret_cast<float4*>(s + i);
        v4.x = __expf(v4.x - m); v4.y = __expf(v4.y - m);
        v4.z = __expf(v4.z - m); v4.w = __expf(v4.w - m);
        sum += v4.x + v4.y + v4.z + v4.w;
        *reinterpret_cast<float4*>(s + i) = v4;
    }
    red[tid] = sum; __syncthreads();
    for (int o = 128; o > 0; o >>= 1) {
        if (tid < o) red[tid] += red[tid + o];
        __syncthreads();
    }
    if (tid == 0) rowsum[row] = red[0];
}

// ---------------------------------------------------------------------------
extern "C" void kernel_launch(void* const* d_in, const int* in_sizes, int n_in,
                              void* d_out, int out_size)
{
    const float* x  = (const float*)d_in[0];
    const float* wq = (const float*)d_in[1];
    const float* wk = (const float*)d_in[2];
    const float* wv = (const float*)d_in[3];
    float* out = (float*)d_out;

    __nv_bfloat16 *x3, *w3, *q3, *k3, *p3, *v3t;
    float *qkv, *s, *rs;
    cudaGetSymbolAddress((void**)&x3,  g_x3);
    cudaGetSymbolAddress((void**)&w3,  g_w3);
    cudaGetSymbolAddress((void**)&qkv, g_qkv);
    cudaGetSymbolAddress((void**)&q3,  g_q3);
    cudaGetSymbolAddress((void**)&k3,  g_k3);
    cudaGetSymbolAddress((void**)&s,   g_s);
    cudaGetSymbolAddress((void**)&p3,  g_p3);
    cudaGetSymbolAddress((void**)&v3t, g_v3t);
    cudaGetSymbolAddress((void**)&rs,  g_rowsum);

    cudaFuncSetAttribute(gemm_bf16_tc, cudaFuncAttributeMaxDynamicSharedMemorySize,
                         GEMM_SMEM_BYTES);

    dim3 blk(256);
    const int CV = 256 * 4;

    // Split inputs
    convert_split<<<(N_TOK * DMODEL) / CV, blk>>>(x, DMODEL, N_TOK, DMODEL, x3, 0);
    convert_split<<<(DMODEL * DMODEL) / CV, blk>>>(wq, DMODEL, DMODEL, DMODEL, w3, 1);
    convert_split<<<(DMODEL * DMODEL) / CV, blk>>>(wk, DMODEL, DMODEL, DMODEL,
                                                   w3 + (size_t)DMODEL * 3 * DMODEL, 1);
    convert_split<<<(DMODEL * DMODEL) / CV, blk>>>(wv, DMODEL, DMODEL, DMODEL,
                                                   w3 + (size_t)2 * DMODEL * 3 * DMODEL, 1);

    // qkv[4096, 3072] = x @ [wq|wk|wv]^T
    gemm_bf16_tc<<<dim3(3 * DMODEL / 128, N_TOK / 128), blk, GEMM_SMEM_BYTES>>>(
        x3, w3, qkv, 3 * DMODEL, 3 * DMODEL, 1.0f, nullptr);

    // Split q, k; transpose+split v
    convert_split<<<(N_TOK * DMODEL) / CV, blk>>>(qkv, 3 * DMODEL, N_TOK, DMODEL, q3, 0);
    convert_split<<<(N_TOK * DMODEL) / CV, blk>>>(qkv + DMODEL, 3 * DMODEL, N_TOK, DMODEL, k3, 1);
    transpose_split_v<<<dim3(DMODEL / 32, N_TOK / 32), blk>>>(qkv + 2 * DMODEL, 3 * DMODEL, v3t);

    // scores = (q @ k^T) / 32
    gemm_bf16_tc<<<dim3(N_TOK / 128, N_TOK / 128), blk, GEMM_SMEM_BYTES>>>(
        q3, k3, s, 3 * DMODEL, N_TOK, 1.0f / 32.0f, nullptr);

    // in-place exp(s - rowmax), rowsum
    softmax_rows<<<N_TOK, blk>>>(s, rs);

    // Split P
    convert_split<<<(N_TOK * N_TOK) / CV, blk>>>(s, N_TOK, N_TOK, N_TOK, p3, 0);

    // out = (P @ v) / rowsum
    gemm_bf16_tc<<<dim3(DMODEL / 128, N_TOK / 128), blk, GEMM_SMEM_BYTES>>>(
        p3, v3t, out, 3 * N_TOK, DMODEL, 1.0f, rs);
}

// round 4
// speedup vs baseline: 2.8235x; 1.0268x over previous
#include <cuda_runtime.h>
#include <cuda_bf16.h>
#include <math.h>
#include <stdint.h>

#define N_TOK 4096
#define DMODEL 1024

// ---------------------------------------------------------------------------
// Scratch (device globals)
// ---------------------------------------------------------------------------
__device__ __nv_bfloat16 g_x3[(size_t)N_TOK * 3 * DMODEL];          // [4096, 3072]
__device__ __nv_bfloat16 g_w3[(size_t)3 * DMODEL * 3 * DMODEL];     // [3072, 3072]
__device__ float         g_qkv[(size_t)N_TOK * 3 * DMODEL];         // [4096, 3072]
__device__ __nv_bfloat16 g_q3[(size_t)N_TOK * 3 * DMODEL];          // [4096, 3072]
__device__ __nv_bfloat16 g_k3[(size_t)N_TOK * 3 * DMODEL];          // [4096, 3072]
__device__ float         g_s[(size_t)N_TOK * N_TOK];                // [4096, 4096]
__device__ __nv_bfloat16 g_p3[(size_t)N_TOK * 3 * N_TOK];           // [4096, 12288]
__device__ __nv_bfloat16 g_v3t[(size_t)DMODEL * 3 * N_TOK];         // [1024, 12288]
__device__ float         g_rowsum[N_TOK];

// ---------------------------------------------------------------------------
// PTX helpers (baseline sm_80+ instructions only)
// ---------------------------------------------------------------------------
__device__ __forceinline__ uint32_t smem_u32(const void* p) {
    uint32_t a;
    asm("{ .reg .u64 t; cvta.to.shared.u64 t, %1; cvt.u32.u64 %0, t; }" : "=r"(a) : "l"(p));
    return a;
}
__device__ __forceinline__ void cp_async16(uint32_t saddr, const void* gptr) {
    asm volatile("cp.async.cg.shared.global [%0], [%1], 16;" :: "r"(saddr), "l"(gptr) : "memory");
}
__device__ __forceinline__ void cp_commit() {
    asm volatile("cp.async.commit_group;" ::: "memory");
}
__device__ __forceinline__ void cp_wait1() {
    asm volatile("cp.async.wait_group 1;" ::: "memory");
}
__device__ __forceinline__ void ldsm_x4(uint32_t& r0, uint32_t& r1, uint32_t& r2, uint32_t& r3,
                                        uint32_t addr) {
    asm volatile("ldmatrix.sync.aligned.m8n8.x4.shared.b16 {%0,%1,%2,%3}, [%4];"
                 : "=r"(r0), "=r"(r1), "=r"(r2), "=r"(r3) : "r"(addr));
}
__device__ __forceinline__ void mma_bf16(float& c0, float& c1, float& c2, float& c3,
                                         uint32_t a0, uint32_t a1, uint32_t a2, uint32_t a3,
                                         uint32_t b0, uint32_t b1) {
    asm volatile(
        "mma.sync.aligned.m16n8k16.row.col.f32.bf16.bf16.f32 "
        "{%0,%1,%2,%3}, {%4,%5,%6,%7}, {%8,%9}, {%0,%1,%2,%3};"
        : "+f"(c0), "+f"(c1), "+f"(c2), "+f"(c3)
        : "r"(a0), "r"(a1), "r"(a2), "r"(a3), "r"(b0), "r"(b1));
}
#define SW128(b) ((b) ^ (((b) >> 3) & 0x70))

// ---------------------------------------------------------------------------
// bf16 tensor-core GEMM (NT): C[M,N] = scale * A[M,Kb] @ B[N,Kb]^T
// CTA tile 128x256, BK=64, 3-stage cp.async, 8 warps (2x4), warp tile 64x64.
// scale = alpha, or 1/rowsum[row] when rowsum != nullptr.
// ---------------------------------------------------------------------------
#define STAGES 3
#define STAGE_BYTES 49152            // A 16KB + B 32KB
#define GEMM_SMEM_BYTES (STAGES * STAGE_BYTES)

__global__ __launch_bounds__(256, 1)
void gemm_bf16_tc(const __nv_bfloat16* __restrict__ A,
                  const __nv_bfloat16* __restrict__ B,
                  float* __restrict__ C, int Kb, int ldc, float alpha,
                  const float* __restrict__ rowsum)
{
    extern __shared__ char smem[];
    const uint32_t sbase = smem_u32(smem);

    const int tid  = threadIdx.x;
    const int wid  = tid >> 5;
    const int lane = tid & 31;
    const int warp_m = wid >> 2;    // 0..1  (64-row slab)
    const int warp_n = wid & 3;     // 0..3  (64-col slab)

    const int m0 = blockIdx.y * 128;
    const int n0 = blockIdx.x * 256;
    const int T  = Kb >> 6;

    const __nv_bfloat16* Ab = A + (size_t)m0 * Kb;
    const __nv_bfloat16* Bb = B + (size_t)n0 * Kb;

    // ldmatrix loop-invariant address pieces
    const uint32_t a_row = (uint32_t)(warp_m * 64 + (lane & 15)) * 128;
    const uint32_t a_chk = (uint32_t)(lane >> 4) * 16;
    const uint32_t b_row = (uint32_t)(warp_n * 64 + (lane & 7) + ((lane >> 4) & 1) * 8) * 128;
    const uint32_t b_chk = (uint32_t)((lane >> 3) & 1) * 16;

    float acc[4][8][4];
#pragma unroll
    for (int mi = 0; mi < 4; mi++)
#pragma unroll
        for (int ni = 0; ni < 8; ni++)
#pragma unroll
            for (int e = 0; e < 4; e++) acc[mi][ni][e] = 0.0f;

    // -------- prologue: issue stages 0 and 1 --------
#pragma unroll
    for (int p = 0; p < 2; p++) {
        const uint32_t sa = sbase + p * STAGE_BYTES;
        const uint32_t sb = sa + 16384;
        const int k0 = p << 6;
#pragma unroll
        for (int j = 0; j < 4; j++) {
            int chunk = tid + j * 256;
            int r = chunk >> 3, c16 = chunk & 7;
            cp_async16(sa + SW128((uint32_t)(r * 128 + c16 * 16)),
                       Ab + (size_t)r * Kb + k0 + c16 * 8);
        }
#pragma unroll
        for (int j = 0; j < 8; j++) {
            int chunk = tid + j * 256;
            int r = chunk >> 3, c16 = chunk & 7;
            cp_async16(sb + SW128((uint32_t)(r * 128 + c16 * 16)),
                       Bb + (size_t)r * Kb + k0 + c16 * 8);
        }
        cp_commit();
    }

    // -------- mainloop --------
    for (int i = 0; i < T; i++) {
        cp_wait1();
        __syncthreads();

        // issue tile i+2 (overlaps with compute below)
        if (i + 2 < T) {
            const int s2 = (i + 2) % STAGES;
            const uint32_t sa = sbase + s2 * STAGE_BYTES;
            const uint32_t sb = sa + 16384;
            const int k0 = (i + 2) << 6;
#pragma unroll
            for (int j = 0; j < 4; j++) {
                int chunk = tid + j * 256;
                int r = chunk >> 3, c16 = chunk & 7;
                cp_async16(sa + SW128((uint32_t)(r * 128 + c16 * 16)),
                           Ab + (size_t)r * Kb + k0 + c16 * 8);
            }
#pragma unroll
            for (int j = 0; j < 8; j++) {
                int chunk = tid + j * 256;
                int r = chunk >> 3, c16 = chunk & 7;
                cp_async16(sb + SW128((uint32_t)(r * 128 + c16 * 16)),
                           Bb + (size_t)r * Kb + k0 + c16 * 8);
            }
        }
        cp_commit();

        // compute tile i
        const uint32_t sa = sbase + (i % STAGES) * STAGE_BYTES;
        const uint32_t sb = sa + 16384;
#pragma unroll
        for (int kk = 0; kk < 4; kk++) {
            uint32_t a[4][4];
            uint32_t b[8][2];
#pragma unroll
            for (int mi = 0; mi < 4; mi++) {
                uint32_t addr = sa + SW128(a_row + (uint32_t)(mi * 16 * 128) +
                                           (uint32_t)(kk * 32) + a_chk);
                ldsm_x4(a[mi][0], a[mi][1], a[mi][2], a[mi][3], addr);
            }
#pragma unroll
            for (int np = 0; np < 4; np++) {
                uint32_t addr = sb + SW128(b_row + (uint32_t)(np * 16 * 128) +
                                           (uint32_t)(kk * 32) + b_chk);
                uint32_t r0, r1, r2, r3;
                ldsm_x4(r0, r1, r2, r3, addr);
                b[np * 2 + 0][0] = r0; b[np * 2 + 0][1] = r1;
                b[np * 2 + 1][0] = r2; b[np * 2 + 1][1] = r3;
            }
#pragma unroll
            for (int mi = 0; mi < 4; mi++)
#pragma unroll
                for (int ni = 0; ni < 8; ni++)
                    mma_bf16(acc[mi][ni][0], acc[mi][ni][1], acc[mi][ni][2], acc[mi][ni][3],
                             a[mi][0], a[mi][1], a[mi][2], a[mi][3],
                             b[ni][0], b[ni][1]);
        }
        __syncthreads();
    }

    // -------- epilogue --------
    const int col_base = n0 + warp_n * 64 + (lane & 3) * 2;
    const int row_base = m0 + warp_m * 64 + (lane >> 2);
#pragma unroll
    for (int mi = 0; mi < 4; mi++) {
        const int r0 = row_base + mi * 16;
        const int r1 = r0 + 8;
        float sc0, sc1;
        if (rowsum) { sc0 = 1.0f / rowsum[r0]; sc1 = 1.0f / rowsum[r1]; }
        else        { sc0 = alpha; sc1 = alpha; }
        float* C0 = C + (size_t)r0 * ldc;
        float* C1 = C + (size_t)r1 * ldc;
#pragma unroll
        for (int ni = 0; ni < 8; ni++) {
            const int c = col_base + ni * 8;
            *reinterpret_cast<float2*>(C0 + c) =
                make_float2(acc[mi][ni][0] * sc0, acc[mi][ni][1] * sc0);
            *reinterpret_cast<float2*>(C1 + c) =
                make_float2(acc[mi][ni][2] * sc1, acc[mi][ni][3] * sc1);
        }
    }
}

// ---------------------------------------------------------------------------
// Split-convert: in fp32 [R, C] (leading dim ld) -> out bf16 [R, 3C]
// patB==0: [hi | hi | lo]   patB==1: [hi | lo | hi]
// ---------------------------------------------------------------------------
__global__ __launch_bounds__(256) void convert_split(
    const float* __restrict__ in, int ld, int R, int C,
    __nv_bfloat16* __restrict__ out, int patB)
{
    size_t idx = ((size_t)blockIdx.x * 256 + threadIdx.x) * 4;
    size_t total = (size_t)R * C;
    if (idx >= total) return;
    int r = (int)(idx / C);
    int c = (int)(idx % C);
    float4 v = *reinterpret_cast<const float4*>(in + (size_t)r * ld + c);
    float vv[4] = {v.x, v.y, v.z, v.w};
    __nv_bfloat16 hi[4], lo[4];
#pragma unroll
    for (int i = 0; i < 4; i++) {
        hi[i] = __float2bfloat16(vv[i]);
        lo[i] = __float2bfloat16(vv[i] - __bfloat162float(hi[i]));
    }
    size_t ob = (size_t)r * 3 * C + c;
    __nv_bfloat16* o0 = out + ob;
    __nv_bfloat16* o1 = out + ob + C;
    __nv_bfloat16* o2 = out + ob + 2 * C;
#pragma unroll
    for (int i = 0; i < 4; i++) {
        o0[i] = hi[i];
        o1[i] = patB ? lo[i] : hi[i];
        o2[i] = patB ? hi[i] : lo[i];
    }
}

// ---------------------------------------------------------------------------
// Transpose + split-convert for V: in fp32 [4096(K), 1024(N)] (ld given) ->
// out bf16 [1024, 12288] = [vh | vl | vh] along cols.
// ---------------------------------------------------------------------------
__global__ __launch_bounds__(256) void transpose_split_v(
    const float* __restrict__ in, int ld, __nv_bfloat16* __restrict__ out)
{
    __shared__ float tile[32][33];
    int n0 = blockIdx.x * 32;
    int k0 = blockIdx.y * 32;
    int tx = threadIdx.x & 31;
    int ty = threadIdx.x >> 5;
#pragma unroll
    for (int l = 0; l < 4; l++)
        tile[ty + 8 * l][tx] = in[(size_t)(k0 + ty + 8 * l) * ld + n0 + tx];
    __syncthreads();
#pragma unroll
    for (int l = 0; l < 4; l++) {
        int n = n0 + ty + 8 * l;
        float v = tile[tx][ty + 8 * l];
        __nv_bfloat16 hi = __float2bfloat16(v);
        __nv_bfloat16 lo = __float2bfloat16(v - __bfloat162float(hi));
        size_t ob = (size_t)n * (3 * N_TOK) + k0 + tx;
        out[ob] = hi;
        out[ob + N_TOK] = lo;
        out[ob + 2 * N_TOK] = hi;
    }
}

// ---------------------------------------------------------------------------
// Fused softmax + P split: reads s[row], computes exp(s-max) in registers,
// writes p3 = [hi | hi | lo] bf16 directly, and rowsum.
// One block (256 thr) per row; 16 elements per thread held in registers.
// ---------------------------------------------------------------------------
__global__ __launch_bounds__(256) void softmax_p3(
    const float* __restrict__ S, __nv_bfloat16* __restrict__ P3,
    float* __restrict__ rowsum)
{
    __shared__ float red[256];
    const int row = blockIdx.x;
    const int tid = threadIdx.x;
    const float* s = S + (size_t)row * N_TOK;

    float4 v[4];
    float m = -INFINITY;
#pragma unroll
    for (int j = 0; j < 4; j++) {
        v[j] = *reinterpret_cast<const float4*>(s + tid * 4 + j * 1024);
        m = fmaxf(m, fmaxf(fmaxf(v[j].x, v[j].y), fmaxf(v[j].z, v[j].w)));
    }
    red[tid] = m; __syncthreads();
    for (int o = 128; o > 0; o >>= 1) {
        if (tid < o) red[tid] = fmaxf(red[tid], red[tid + o]);
        __syncthreads();
    }
    m = red[0]; __syncthreads();

    float sum = 0.0f;
#pragma unroll
    for (int j = 0; j < 4; j++) {
        v[j].x = __expf(v[j].x - m); v[j].y = __expf(v[j].y - m);
        v[j].z = __expf(v[j].z - m); v[j].w = __expf(v[j].w - m);
        sum += v[j].x + v[j].y + v[j].z + v[j].w;
    }
    red[tid] = sum; __syncthreads();
    for (int o = 128; o > 0; o >>= 1) {
        if (tid < o) red[tid] += red[tid + o];
        __syncthreads();
    }
    if (tid == 0) rowsum[row] = red[0];

    __nv_bfloat16* p = P3 + (size_t)row * 3 * N_TOK;
#pragma unroll
    for (int j = 0; j < 4; j++) {
        const int idx = tid * 4 + j * 1024;
        float vv[4] = {v[j].x, v[j].y, v[j].z, v[j].w};
        union { __nv_bfloat16 h[4]; uint2 u; } ph, pl;
#pragma unroll
        for (int i = 0; i < 4; i++) {
            ph.h[i] = __float2bfloat16(vv[i]);
            pl.h[i] = __float2bfloat16(vv[i] - __bfloat162float(ph.h[i]));
        }
        *reinterpret_cast<uint2*>(p + idx)              = ph.u;
        *reinterpret_cast<uint2*>(p + idx + N_TOK)      = ph.u;
        *reinterpret_cast<uint2*>(p + idx + 2 * N_TOK)  = pl.u;
    }
}

// ---------------------------------------------------------------------------
extern "C" void kernel_launch(void* const* d_in, const int* in_sizes, int n_in,
                              void* d_out, int out_size)
{
    const float* x  = (const float*)d_in[0];
    const float* wq = (const float*)d_in[1];
    const float* wk = (const float*)d_in[2];
    const float* wv = (const float*)d_in[3];
    float* out = (float*)d_out;

    __nv_bfloat16 *x3, *w3, *q3, *k3, *p3, *v3t;
    float *qkv, *s, *rs;
    cudaGetSymbolAddress((void**)&x3,  g_x3);
    cudaGetSymbolAddress((void**)&w3,  g_w3);
    cudaGetSymbolAddress((void**)&qkv, g_qkv);
    cudaGetSymbolAddress((void**)&q3,  g_q3);
    cudaGetSymbolAddress((void**)&k3,  g_k3);
    cudaGetSymbolAddress((void**)&s,   g_s);
    cudaGetSymbolAddress((void**)&p3,  g_p3);
    cudaGetSymbolAddress((void**)&v3t, g_v3t);
    cudaGetSymbolAddress((void**)&rs,  g_rowsum);

    cudaFuncSetAttribute(gemm_bf16_tc, cudaFuncAttributeMaxDynamicSharedMemorySize,
                         GEMM_SMEM_BYTES);

    dim3 blk(256);
    const int CV = 256 * 4;

    // Split inputs
    convert_split<<<(N_TOK * DMODEL) / CV, blk>>>(x, DMODEL, N_TOK, DMODEL, x3, 0);
    convert_split<<<(DMODEL * DMODEL) / CV, blk>>>(wq, DMODEL, DMODEL, DMODEL, w3, 1);
    convert_split<<<(DMODEL * DMODEL) / CV, blk>>>(wk, DMODEL, DMODEL, DMODEL,
                                                   w3 + (size_t)DMODEL * 3 * DMODEL, 1);
    convert_split<<<(DMODEL * DMODEL) / CV, blk>>>(wv, DMODEL, DMODEL, DMODEL,
                                                   w3 + (size_t)2 * DMODEL * 3 * DMODEL, 1);

    // qkv[4096, 3072] = x @ [wq|wk|wv]^T
    gemm_bf16_tc<<<dim3(3 * DMODEL / 256, N_TOK / 128), blk, GEMM_SMEM_BYTES>>>(
        x3, w3, qkv, 3 * DMODEL, 3 * DMODEL, 1.0f, nullptr);

    // Split q, k; transpose+split v
    convert_split<<<(N_TOK * DMODEL) / CV, blk>>>(qkv, 3 * DMODEL, N_TOK, DMODEL, q3, 0);
    convert_split<<<(N_TOK * DMODEL) / CV, blk>>>(qkv + DMODEL, 3 * DMODEL, N_TOK, DMODEL, k3, 1);
    transpose_split_v<<<dim3(DMODEL / 32, N_TOK / 32), blk>>>(qkv + 2 * DMODEL, 3 * DMODEL, v3t);

    // scores = (q @ k^T) / 32
    gemm_bf16_tc<<<dim3(N_TOK / 256, N_TOK / 128), blk, GEMM_SMEM_BYTES>>>(
        q3, k3, s, 3 * DMODEL, N_TOK, 1.0f / 32.0f, nullptr);

    // fused softmax + P split
    softmax_p3<<<N_TOK, blk>>>(s, p3, rs);

    // out = (P @ v) / rowsum
    gemm_bf16_tc<<<dim3(DMODEL / 256, N_TOK / 128), blk, GEMM_SMEM_BYTES>>>(
        p3, v3t, out, 3 * N_TOK, DMODEL, 1.0f, rs);
}

// round 5
// speedup vs baseline: 2.9037x; 1.0284x over previous
#include <cuda_runtime.h>
#include <cuda_bf16.h>
#include <math.h>
#include <stdint.h>

#define N_TOK 4096
#define DMODEL 1024

// ---------------------------------------------------------------------------
// Scratch (device globals)
// ---------------------------------------------------------------------------
__device__ __nv_bfloat16 g_x3[(size_t)N_TOK * 3 * DMODEL];          // [4096, 3072]
__device__ __nv_bfloat16 g_w3[(size_t)3 * DMODEL * 3 * DMODEL];     // [3072, 3072]
__device__ float         g_vbuf[(size_t)N_TOK * DMODEL];            // [4096, 1024]
__device__ __nv_bfloat16 g_q3[(size_t)N_TOK * 3 * DMODEL];          // [4096, 3072]
__device__ __nv_bfloat16 g_k3[(size_t)N_TOK * 3 * DMODEL];          // [4096, 3072]
__device__ float         g_s[(size_t)N_TOK * N_TOK];                // [4096, 4096]
__device__ __nv_bfloat16 g_p3[(size_t)N_TOK * 3 * N_TOK];           // [4096, 12288]
__device__ __nv_bfloat16 g_v3t[(size_t)DMODEL * 3 * N_TOK];         // [1024, 12288]
__device__ float         g_rowsum[N_TOK];

// ---------------------------------------------------------------------------
// PTX helpers (baseline sm_80+ instructions only)
// ---------------------------------------------------------------------------
__device__ __forceinline__ uint32_t smem_u32(const void* p) {
    uint32_t a;
    asm("{ .reg .u64 t; cvta.to.shared.u64 t, %1; cvt.u32.u64 %0, t; }" : "=r"(a) : "l"(p));
    return a;
}
__device__ __forceinline__ void cp_async16(uint32_t saddr, const void* gptr) {
    asm volatile("cp.async.cg.shared.global [%0], [%1], 16;" :: "r"(saddr), "l"(gptr) : "memory");
}
__device__ __forceinline__ void cp_commit() {
    asm volatile("cp.async.commit_group;" ::: "memory");
}
__device__ __forceinline__ void cp_wait1() {
    asm volatile("cp.async.wait_group 1;" ::: "memory");
}
__device__ __forceinline__ void ldsm_x4(uint32_t& r0, uint32_t& r1, uint32_t& r2, uint32_t& r3,
                                        uint32_t addr) {
    asm volatile("ldmatrix.sync.aligned.m8n8.x4.shared.b16 {%0,%1,%2,%3}, [%4];"
                 : "=r"(r0), "=r"(r1), "=r"(r2), "=r"(r3) : "r"(addr));
}
__device__ __forceinline__ void mma_bf16(float& c0, float& c1, float& c2, float& c3,
                                         uint32_t a0, uint32_t a1, uint32_t a2, uint32_t a3,
                                         uint32_t b0, uint32_t b1) {
    asm volatile(
        "mma.sync.aligned.m16n8k16.row.col.f32.bf16.bf16.f32 "
        "{%0,%1,%2,%3}, {%4,%5,%6,%7}, {%8,%9}, {%0,%1,%2,%3};"
        : "+f"(c0), "+f"(c1), "+f"(c2), "+f"(c3)
        : "r"(a0), "r"(a1), "r"(a2), "r"(a3), "r"(b0), "r"(b1));
}
#define SW128(b) ((b) ^ (((b) >> 3) & 0x70))

__device__ __forceinline__ uint32_t pack_bf16x2(float a, float b) {
    __nv_bfloat162 h = __floats2bfloat162_rn(a, b);
    return *reinterpret_cast<uint32_t*>(&h);
}

// ---------------------------------------------------------------------------
// bf16 tensor-core GEMM (NT): CTA tile 128x256, BK=64, 3-stage cp.async,
// 8 warps (2x4), warp tile 64x64, fragment double-buffering over kk.
// MODE 0: C = alpha * A@B^T (fp32)
// MODE 1: C = A@B^T / rowsum[row]
// MODE 2: QKV fused epilogue: col region 0 -> q3 split [hi|hi|lo],
//         region 1 -> k3 split [hi|lo|hi], region 2 -> vbuf fp32 (ld 1024)
// ---------------------------------------------------------------------------
#define STAGES 3
#define STAGE_BYTES 49152            // A 16KB + B 32KB
#define GEMM_SMEM_BYTES (STAGES * STAGE_BYTES)

template<int MODE>
__global__ __launch_bounds__(256, 1)
void gemm_tc(const __nv_bfloat16* __restrict__ A,
             const __nv_bfloat16* __restrict__ B,
             float* __restrict__ C, int Kb, int ldc, float alpha,
             const float* __restrict__ rowsum,
             __nv_bfloat16* __restrict__ q3,
             __nv_bfloat16* __restrict__ k3,
             float* __restrict__ vbuf)
{
    extern __shared__ char smem[];
    const uint32_t sbase = smem_u32(smem);

    const int tid  = threadIdx.x;
    const int wid  = tid >> 5;
    const int lane = tid & 31;
    const int warp_m = wid >> 2;
    const int warp_n = wid & 3;

    const int m0 = blockIdx.y * 128;
    const int n0 = blockIdx.x * 256;
    const int T  = Kb >> 6;

    const __nv_bfloat16* Ab = A + (size_t)m0 * Kb;
    const __nv_bfloat16* Bb = B + (size_t)n0 * Kb;

    const uint32_t a_row = (uint32_t)(warp_m * 64 + (lane & 15)) * 128;
    const uint32_t a_chk = (uint32_t)(lane >> 4) * 16;
    const uint32_t b_row = (uint32_t)(warp_n * 64 + (lane & 7) + ((lane >> 4) & 1) * 8) * 128;
    const uint32_t b_chk = (uint32_t)((lane >> 3) & 1) * 16;

    float acc[4][8][4];
#pragma unroll
    for (int mi = 0; mi < 4; mi++)
#pragma unroll
        for (int ni = 0; ni < 8; ni++)
#pragma unroll
            for (int e = 0; e < 4; e++) acc[mi][ni][e] = 0.0f;

    // -------- prologue: issue stages 0 and 1 --------
#pragma unroll
    for (int p = 0; p < 2; p++) {
        const uint32_t sa = sbase + p * STAGE_BYTES;
        const uint32_t sb = sa + 16384;
        const int k0 = p << 6;
#pragma unroll
        for (int j = 0; j < 4; j++) {
            int chunk = tid + j * 256;
            int r = chunk >> 3, c16 = chunk & 7;
            cp_async16(sa + SW128((uint32_t)(r * 128 + c16 * 16)),
                       Ab + (size_t)r * Kb + k0 + c16 * 8);
        }
#pragma unroll
        for (int j = 0; j < 8; j++) {
            int chunk = tid + j * 256;
            int r = chunk >> 3, c16 = chunk & 7;
            cp_async16(sb + SW128((uint32_t)(r * 128 + c16 * 16)),
                       Bb + (size_t)r * Kb + k0 + c16 * 8);
        }
        cp_commit();
    }

    uint32_t afr[2][4][4];
    uint32_t bfr[2][8][2];

    // -------- mainloop --------
    for (int i = 0; i < T; i++) {
        cp_wait1();
        __syncthreads();

        // issue tile i+2 (overlaps with compute below)
        if (i + 2 < T) {
            const int s2 = (i + 2) % STAGES;
            const uint32_t sa = sbase + s2 * STAGE_BYTES;
            const uint32_t sb = sa + 16384;
            const int k0 = (i + 2) << 6;
#pragma unroll
            for (int j = 0; j < 4; j++) {
                int chunk = tid + j * 256;
                int r = chunk >> 3, c16 = chunk & 7;
                cp_async16(sa + SW128((uint32_t)(r * 128 + c16 * 16)),
                           Ab + (size_t)r * Kb + k0 + c16 * 8);
            }
#pragma unroll
            for (int j = 0; j < 8; j++) {
                int chunk = tid + j * 256;
                int r = chunk >> 3, c16 = chunk & 7;
                cp_async16(sb + SW128((uint32_t)(r * 128 + c16 * 16)),
                           Bb + (size_t)r * Kb + k0 + c16 * 8);
            }
        }
        cp_commit();

        // compute tile i with fragment double-buffering over kk
        const uint32_t sa = sbase + (i % STAGES) * STAGE_BYTES;
        const uint32_t sb = sa + 16384;

        // load kk=0 fragments
#pragma unroll
        for (int mi = 0; mi < 4; mi++) {
            uint32_t addr = sa + SW128(a_row + (uint32_t)(mi * 16 * 128) + a_chk);
            ldsm_x4(afr[0][mi][0], afr[0][mi][1], afr[0][mi][2], afr[0][mi][3], addr);
        }
#pragma unroll
        for (int np = 0; np < 4; np++) {
            uint32_t addr = sb + SW128(b_row + (uint32_t)(np * 16 * 128) + b_chk);
            uint32_t r0, r1, r2, r3;
            ldsm_x4(r0, r1, r2, r3, addr);
            bfr[0][np * 2 + 0][0] = r0; bfr[0][np * 2 + 0][1] = r1;
            bfr[0][np * 2 + 1][0] = r2; bfr[0][np * 2 + 1][1] = r3;
        }

#pragma unroll
        for (int kk = 0; kk < 4; kk++) {
            const int cur = kk & 1, nxt = cur ^ 1;
            if (kk < 3) {
#pragma unroll
                for (int mi = 0; mi < 4; mi++) {
                    uint32_t addr = sa + SW128(a_row + (uint32_t)(mi * 16 * 128) +
                                               (uint32_t)((kk + 1) * 32) + a_chk);
                    ldsm_x4(afr[nxt][mi][0], afr[nxt][mi][1], afr[nxt][mi][2], afr[nxt][mi][3], addr);
                }
#pragma unroll
                for (int np = 0; np < 4; np++) {
                    uint32_t addr = sb + SW128(b_row + (uint32_t)(np * 16 * 128) +
                                               (uint32_t)((kk + 1) * 32) + b_chk);
                    uint32_t r0, r1, r2, r3;
                    ldsm_x4(r0, r1, r2, r3, addr);
                    bfr[nxt][np * 2 + 0][0] = r0; bfr[nxt][np * 2 + 0][1] = r1;
                    bfr[nxt][np * 2 + 1][0] = r2; bfr[nxt][np * 2 + 1][1] = r3;
                }
            }
#pragma unroll
            for (int mi = 0; mi < 4; mi++)
#pragma unroll
                for (int ni = 0; ni < 8; ni++)
                    mma_bf16(acc[mi][ni][0], acc[mi][ni][1], acc[mi][ni][2], acc[mi][ni][3],
                             afr[cur][mi][0], afr[cur][mi][1], afr[cur][mi][2], afr[cur][mi][3],
                             bfr[cur][ni][0], bfr[cur][ni][1]);
        }
        // no trailing __syncthreads: top-of-loop barrier protects stage reuse
    }

    // -------- epilogue --------
    const int col_off = warp_n * 64 + (lane & 3) * 2;   // col within 256-slab
    const int row_base = m0 + warp_m * 64 + (lane >> 2);

#pragma unroll
    for (int mi = 0; mi < 4; mi++) {
        const int r0 = row_base + mi * 16;
        const int r1 = r0 + 8;
        if (MODE == 2) {
            const int region = n0 >> 10;            // 0=q, 1=k, 2=v
            const int nc0 = (n0 & 1023) + col_off;  // col within 1024 region
#pragma unroll
            for (int ni = 0; ni < 8; ni++) {
                const int c = nc0 + ni * 8;
                float v00 = acc[mi][ni][0], v01 = acc[mi][ni][1];
                float v10 = acc[mi][ni][2], v11 = acc[mi][ni][3];
                if (region == 2) {
                    *reinterpret_cast<float2*>(vbuf + (size_t)r0 * DMODEL + c) = make_float2(v00, v01);
                    *reinterpret_cast<float2*>(vbuf + (size_t)r1 * DMODEL + c) = make_float2(v10, v11);
                } else {
                    uint32_t hi0 = pack_bf16x2(v00, v01);
                    uint32_t hi1 = pack_bf16x2(v10, v11);
                    __nv_bfloat162 h0 = *reinterpret_cast<__nv_bfloat162*>(&hi0);
                    __nv_bfloat162 h1 = *reinterpret_cast<__nv_bfloat162*>(&hi1);
                    uint32_t lo0 = pack_bf16x2(v00 - __bfloat162float(h0.x),
                                               v01 - __bfloat162float(h0.y));
                    uint32_t lo1 = pack_bf16x2(v10 - __bfloat162float(h1.x),
                                               v11 - __bfloat162float(h1.y));
                    __nv_bfloat16* dst = (region == 0) ? q3 : k3;
                    // q: [hi|hi|lo]   k: [hi|lo|hi]
                    uint32_t m0w = hi0, m1w = hi1;                         // +0
                    uint32_t a0w = (region == 0) ? hi0 : lo0;              // +1024
                    uint32_t a1w = (region == 0) ? hi1 : lo1;
                    uint32_t b0w = (region == 0) ? lo0 : hi0;              // +2048
                    uint32_t b1w = (region == 0) ? lo1 : hi1;
                    __nv_bfloat16* p0 = dst + (size_t)r0 * (3 * DMODEL) + c;
                    __nv_bfloat16* p1 = dst + (size_t)r1 * (3 * DMODEL) + c;
                    *reinterpret_cast<uint32_t*>(p0)            = m0w;
                    *reinterpret_cast<uint32_t*>(p0 + DMODEL)   = a0w;
                    *reinterpret_cast<uint32_t*>(p0 + 2*DMODEL) = b0w;
                    *reinterpret_cast<uint32_t*>(p1)            = m1w;
                    *reinterpret_cast<uint32_t*>(p1 + DMODEL)   = a1w;
                    *reinterpret_cast<uint32_t*>(p1 + 2*DMODEL) = b1w;
                }
            }
        } else {
            float sc0, sc1;
            if (MODE == 1) { sc0 = 1.0f / rowsum[r0]; sc1 = 1.0f / rowsum[r1]; }
            else           { sc0 = alpha; sc1 = alpha; }
            float* C0 = C + (size_t)r0 * ldc + n0;
            float* C1 = C + (size_t)r1 * ldc + n0;
#pragma unroll
            for (int ni = 0; ni < 8; ni++) {
                const int c = col_off + ni * 8;
                *reinterpret_cast<float2*>(C0 + c) =
                    make_float2(acc[mi][ni][0] * sc0, acc[mi][ni][1] * sc0);
                *reinterpret_cast<float2*>(C1 + c) =
                    make_float2(acc[mi][ni][2] * sc1, acc[mi][ni][3] * sc1);
            }
        }
    }
}

// ---------------------------------------------------------------------------
// Split-convert: in fp32 [R, C] (leading dim ld) -> out bf16 [R, 3C]
// patB==0: [hi | hi | lo]   patB==1: [hi | lo | hi]
// ---------------------------------------------------------------------------
__global__ __launch_bounds__(256) void convert_split(
    const float* __restrict__ in, int ld, int R, int C,
    __nv_bfloat16* __restrict__ out, int patB)
{
    size_t idx = ((size_t)blockIdx.x * 256 + threadIdx.x) * 4;
    size_t total = (size_t)R * C;
    if (idx >= total) return;
    int r = (int)(idx / C);
    int c = (int)(idx % C);
    float4 v = *reinterpret_cast<const float4*>(in + (size_t)r * ld + c);
    float vv[4] = {v.x, v.y, v.z, v.w};
    __nv_bfloat16 hi[4], lo[4];
#pragma unroll
    for (int i = 0; i < 4; i++) {
        hi[i] = __float2bfloat16(vv[i]);
        lo[i] = __float2bfloat16(vv[i] - __bfloat162float(hi[i]));
    }
    size_t ob = (size_t)r * 3 * C + c;
    __nv_bfloat16* o0 = out + ob;
    __nv_bfloat16* o1 = out + ob + C;
    __nv_bfloat16* o2 = out + ob + 2 * C;
#pragma unroll
    for (int i = 0; i < 4; i++) {
        o0[i] = hi[i];
        o1[i] = patB ? lo[i] : hi[i];
        o2[i] = patB ? hi[i] : lo[i];
    }
}

// ---------------------------------------------------------------------------
// Transpose + split-convert for V: in fp32 [4096(K), 1024(N)] (ld=1024) ->
// out bf16 [1024, 12288] = [vh | vl | vh] along cols.
// ---------------------------------------------------------------------------
__global__ __launch_bounds__(256) void transpose_split_v(
    const float* __restrict__ in, __nv_bfloat16* __restrict__ out)
{
    __shared__ float tile[32][33];
    int n0 = blockIdx.x * 32;
    int k0 = blockIdx.y * 32;
    int tx = threadIdx.x & 31;
    int ty = threadIdx.x >> 5;
#pragma unroll
    for (int l = 0; l < 4; l++)
        tile[ty + 8 * l][tx] = in[(size_t)(k0 + ty + 8 * l) * DMODEL + n0 + tx];
    __syncthreads();
#pragma unroll
    for (int l = 0; l < 4; l++) {
        int n = n0 + ty + 8 * l;
        float v = tile[tx][ty + 8 * l];
        __nv_bfloat16 hi = __float2bfloat16(v);
        __nv_bfloat16 lo = __float2bfloat16(v - __bfloat162float(hi));
        size_t ob = (size_t)n * (3 * N_TOK) + k0 + tx;
        out[ob] = hi;
        out[ob + N_TOK] = lo;
        out[ob + 2 * N_TOK] = hi;
    }
}

// ---------------------------------------------------------------------------
// Fused softmax + P split: reads s[row], computes exp(s-max) in registers,
// writes p3 = [hi | hi | lo] bf16 directly, and rowsum.
// ---------------------------------------------------------------------------
__global__ __launch_bounds__(256) void softmax_p3(
    const float* __restrict__ S, __nv_bfloat16* __restrict__ P3,
    float* __restrict__ rowsum)
{
    __shared__ float red[256];
    const int row = blockIdx.x;
    const int tid = threadIdx.x;
    const float* s = S + (size_t)row * N_TOK;

    float4 v[4];
    float m = -INFINITY;
#pragma unroll
    for (int j = 0; j < 4; j++) {
        v[j] = *reinterpret_cast<const float4*>(s + tid * 4 + j * 1024);
        m = fmaxf(m, fmaxf(fmaxf(v[j].x, v[j].y), fmaxf(v[j].z, v[j].w)));
    }
    red[tid] = m; __syncthreads();
    for (int o = 128; o > 0; o >>= 1) {
        if (tid < o) red[tid] = fmaxf(red[tid], red[tid + o]);
        __syncthreads();
    }
    m = red[0]; __syncthreads();

    float sum = 0.0f;
#pragma unroll
    for (int j = 0; j < 4; j++) {
        v[j].x = __expf(v[j].x - m); v[j].y = __expf(v[j].y - m);
        v[j].z = __expf(v[j].z - m); v[j].w = __expf(v[j].w - m);
        sum += v[j].x + v[j].y + v[j].z + v[j].w;
    }
    red[tid] = sum; __syncthreads();
    for (int o = 128; o > 0; o >>= 1) {
        if (tid < o) red[tid] += red[tid + o];
        __syncthreads();
    }
    if (tid == 0) rowsum[row] = red[0];

    __nv_bfloat16* p = P3 + (size_t)row * 3 * N_TOK;
#pragma unroll
    for (int j = 0; j < 4; j++) {
        const int idx = tid * 4 + j * 1024;
        float vv[4] = {v[j].x, v[j].y, v[j].z, v[j].w};
        union { __nv_bfloat16 h[4]; uint2 u; } ph, pl;
#pragma unroll
        for (int i = 0; i < 4; i++) {
            ph.h[i] = __float2bfloat16(vv[i]);
            pl.h[i] = __float2bfloat16(vv[i] - __bfloat162float(ph.h[i]));
        }
        *reinterpret_cast<uint2*>(p + idx)              = ph.u;
        *reinterpret_cast<uint2*>(p + idx + N_TOK)      = ph.u;
        *reinterpret_cast<uint2*>(p + idx + 2 * N_TOK)  = pl.u;
    }
}

// ---------------------------------------------------------------------------
extern "C" void kernel_launch(void* const* d_in, const int* in_sizes, int n_in,
                              void* d_out, int out_size)
{
    const float* x  = (const float*)d_in[0];
    const float* wq = (const float*)d_in[1];
    const float* wk = (const float*)d_in[2];
    const float* wv = (const float*)d_in[3];
    float* out = (float*)d_out;

    __nv_bfloat16 *x3, *w3, *q3, *k3, *p3, *v3t;
    float *vbuf, *s, *rs;
    cudaGetSymbolAddress((void**)&x3,   g_x3);
    cudaGetSymbolAddress((void**)&w3,   g_w3);
    cudaGetSymbolAddress((void**)&vbuf, g_vbuf);
    cudaGetSymbolAddress((void**)&q3,   g_q3);
    cudaGetSymbolAddress((void**)&k3,   g_k3);
    cudaGetSymbolAddress((void**)&s,    g_s);
    cudaGetSymbolAddress((void**)&p3,   g_p3);
    cudaGetSymbolAddress((void**)&v3t,  g_v3t);
    cudaGetSymbolAddress((void**)&rs,   g_rowsum);

    cudaFuncSetAttribute(gemm_tc<0>, cudaFuncAttributeMaxDynamicSharedMemorySize, GEMM_SMEM_BYTES);
    cudaFuncSetAttribute(gemm_tc<1>, cudaFuncAttributeMaxDynamicSharedMemorySize, GEMM_SMEM_BYTES);
    cudaFuncSetAttribute(gemm_tc<2>, cudaFuncAttributeMaxDynamicSharedMemorySize, GEMM_SMEM_BYTES);

    dim3 blk(256);
    const int CV = 256 * 4;

    // Split inputs
    convert_split<<<(N_TOK * DMODEL) / CV, blk>>>(x, DMODEL, N_TOK, DMODEL, x3, 0);
    convert_split<<<(DMODEL * DMODEL) / CV, blk>>>(wq, DMODEL, DMODEL, DMODEL, w3, 1);
    convert_split<<<(DMODEL * DMODEL) / CV, blk>>>(wk, DMODEL, DMODEL, DMODEL,
                                                   w3 + (size_t)DMODEL * 3 * DMODEL, 1);
    convert_split<<<(DMODEL * DMODEL) / CV, blk>>>(wv, DMODEL, DMODEL, DMODEL,
                                                   w3 + (size_t)2 * DMODEL * 3 * DMODEL, 1);

    // QKV with fused split epilogue: writes q3, k3, vbuf directly
    gemm_tc<2><<<dim3(3 * DMODEL / 256, N_TOK / 128), blk, GEMM_SMEM_BYTES>>>(
        x3, w3, nullptr, 3 * DMODEL, 0, 1.0f, nullptr, q3, k3, vbuf);

    // transpose+split v
    transpose_split_v<<<dim3(DMODEL / 32, N_TOK / 32), blk>>>(vbuf, v3t);

    // scores = (q @ k^T) / 32
    gemm_tc<0><<<dim3(N_TOK / 256, N_TOK / 128), blk, GEMM_SMEM_BYTES>>>(
        q3, k3, s, 3 * DMODEL, N_TOK, 1.0f / 32.0f, nullptr, nullptr, nullptr, nullptr);

    // fused softmax + P split
    softmax_p3<<<N_TOK, blk>>>(s, p3, rs);

    // out = (P @ v) / rowsum
    gemm_tc<1><<<dim3(DMODEL / 256, N_TOK / 128), blk, GEMM_SMEM_BYTES>>>(
        p3, v3t, out, 3 * N_TOK, DMODEL, 1.0f, rs, nullptr, nullptr, nullptr);
}

// round 6
// speedup vs baseline: 3.0722x; 1.0580x over previous
#include <cuda_runtime.h>
#include <cuda_bf16.h>
#include <math.h>
#include <stdint.h>

#define N_TOK 4096
#define DMODEL 1024

// ---------------------------------------------------------------------------
// Scratch (device globals)
// ---------------------------------------------------------------------------
__device__ __nv_bfloat16 g_x3[(size_t)N_TOK * 3 * DMODEL];          // [4096, 3072]
__device__ __nv_bfloat16 g_w3[(size_t)3 * DMODEL * 3 * DMODEL];     // [3072, 3072]
__device__ float         g_vbuf[(size_t)N_TOK * DMODEL];            // [4096, 1024]
__device__ __nv_bfloat16 g_q3[(size_t)N_TOK * 3 * DMODEL];          // [4096, 3072]
__device__ __nv_bfloat16 g_k3[(size_t)N_TOK * 3 * DMODEL];          // [4096, 3072]
__device__ float         g_s[(size_t)N_TOK * N_TOK];                // [4096, 4096]
__device__ __nv_bfloat16 g_p3[(size_t)N_TOK * 3 * N_TOK];           // [4096, 12288]
__device__ __nv_bfloat16 g_v3t[(size_t)DMODEL * 3 * N_TOK];         // [1024, 12288]
__device__ float         g_rowsum[N_TOK];

// ---------------------------------------------------------------------------
// PTX helpers (baseline sm_80+ instructions only)
// ---------------------------------------------------------------------------
__device__ __forceinline__ uint32_t smem_u32(const void* p) {
    uint32_t a;
    asm("{ .reg .u64 t; cvta.to.shared.u64 t, %1; cvt.u32.u64 %0, t; }" : "=r"(a) : "l"(p));
    return a;
}
__device__ __forceinline__ void cp_async16(uint32_t saddr, const void* gptr) {
    asm volatile("cp.async.cg.shared.global [%0], [%1], 16;" :: "r"(saddr), "l"(gptr) : "memory");
}
__device__ __forceinline__ void cp_commit() {
    asm volatile("cp.async.commit_group;" ::: "memory");
}
__device__ __forceinline__ void cp_wait2() {
    asm volatile("cp.async.wait_group 2;" ::: "memory");
}
__device__ __forceinline__ void ldsm_x4(uint32_t& r0, uint32_t& r1, uint32_t& r2, uint32_t& r3,
                                        uint32_t addr) {
    asm volatile("ldmatrix.sync.aligned.m8n8.x4.shared.b16 {%0,%1,%2,%3}, [%4];"
                 : "=r"(r0), "=r"(r1), "=r"(r2), "=r"(r3) : "r"(addr));
}
__device__ __forceinline__ void mma_bf16(float& c0, float& c1, float& c2, float& c3,
                                         uint32_t a0, uint32_t a1, uint32_t a2, uint32_t a3,
                                         uint32_t b0, uint32_t b1) {
    asm volatile(
        "mma.sync.aligned.m16n8k16.row.col.f32.bf16.bf16.f32 "
        "{%0,%1,%2,%3}, {%4,%5,%6,%7}, {%8,%9}, {%0,%1,%2,%3};"
        : "+f"(c0), "+f"(c1), "+f"(c2), "+f"(c3)
        : "r"(a0), "r"(a1), "r"(a2), "r"(a3), "r"(b0), "r"(b1));
}
#define SW128(b) ((b) ^ (((b) >> 3) & 0x70))

__device__ __forceinline__ uint32_t pack_bf16x2(float a, float b) {
    __nv_bfloat162 h = __floats2bfloat162_rn(a, b);
    return *reinterpret_cast<uint32_t*>(&h);
}

// ---------------------------------------------------------------------------
// bf16 tensor-core GEMM (NT): CTA tile 128x256, BK=64, 4-stage cp.async,
// 8 warps (2x4), warp tile 64x64, fragment double-buffering over kk.
// MODE 0: C = alpha * A@B^T (fp32)
// MODE 1: C = A@B^T / rowsum[row]
// MODE 2: QKV fused epilogue: col region 0 -> q3 split [hi|hi|lo],
//         region 1 -> k3 split [hi|lo|hi], region 2 -> vbuf fp32 (ld 1024)
// ---------------------------------------------------------------------------
#define STAGES 4
#define STAGE_BYTES 49152            // A 16KB + B 32KB
#define GEMM_SMEM_BYTES (STAGES * STAGE_BYTES)

template<int MODE>
__global__ __launch_bounds__(256, 1)
void gemm_tc(const __nv_bfloat16* __restrict__ A,
             const __nv_bfloat16* __restrict__ B,
             float* __restrict__ C, int Kb, int ldc, float alpha,
             const float* __restrict__ rowsum,
             __nv_bfloat16* __restrict__ q3,
             __nv_bfloat16* __restrict__ k3,
             float* __restrict__ vbuf)
{
    extern __shared__ char smem[];
    const uint32_t sbase = smem_u32(smem);

    const int tid  = threadIdx.x;
    const int wid  = tid >> 5;
    const int lane = tid & 31;
    const int warp_m = wid >> 2;
    const int warp_n = wid & 3;

    const int m0 = blockIdx.y * 128;
    const int n0 = blockIdx.x * 256;
    const int T  = Kb >> 6;

    const __nv_bfloat16* Ab = A + (size_t)m0 * Kb;
    const __nv_bfloat16* Bb = B + (size_t)n0 * Kb;

    const uint32_t a_row = (uint32_t)(warp_m * 64 + (lane & 15)) * 128;
    const uint32_t a_chk = (uint32_t)(lane >> 4) * 16;
    const uint32_t b_row = (uint32_t)(warp_n * 64 + (lane & 7) + ((lane >> 4) & 1) * 8) * 128;
    const uint32_t b_chk = (uint32_t)((lane >> 3) & 1) * 16;

    float acc[4][8][4];
#pragma unroll
    for (int mi = 0; mi < 4; mi++)
#pragma unroll
        for (int ni = 0; ni < 8; ni++)
#pragma unroll
            for (int e = 0; e < 4; e++) acc[mi][ni][e] = 0.0f;

    // -------- prologue: issue stages 0..2 --------
#pragma unroll
    for (int p = 0; p < 3; p++) {
        const uint32_t sa = sbase + p * STAGE_BYTES;
        const uint32_t sb = sa + 16384;
        const int k0 = p << 6;
#pragma unroll
        for (int j = 0; j < 4; j++) {
            int chunk = tid + j * 256;
            int r = chunk >> 3, c16 = chunk & 7;
            cp_async16(sa + SW128((uint32_t)(r * 128 + c16 * 16)),
                       Ab + (size_t)r * Kb + k0 + c16 * 8);
        }
#pragma unroll
        for (int j = 0; j < 8; j++) {
            int chunk = tid + j * 256;
            int r = chunk >> 3, c16 = chunk & 7;
            cp_async16(sb + SW128((uint32_t)(r * 128 + c16 * 16)),
                       Bb + (size_t)r * Kb + k0 + c16 * 8);
        }
        cp_commit();
    }

    uint32_t afr[2][4][4];
    uint32_t bfr[2][8][2];

    // -------- mainloop --------
    for (int i = 0; i < T; i++) {
        cp_wait2();
        __syncthreads();

        // issue tile i+3 into stage (i+3)%4 (freed by compute of i-1)
        if (i + 3 < T) {
            const int s3 = (i + 3) % STAGES;
            const uint32_t sa = sbase + s3 * STAGE_BYTES;
            const uint32_t sb = sa + 16384;
            const int k0 = (i + 3) << 6;
#pragma unroll
            for (int j = 0; j < 4; j++) {
                int chunk = tid + j * 256;
                int r = chunk >> 3, c16 = chunk & 7;
                cp_async16(sa + SW128((uint32_t)(r * 128 + c16 * 16)),
                           Ab + (size_t)r * Kb + k0 + c16 * 8);
            }
#pragma unroll
            for (int j = 0; j < 8; j++) {
                int chunk = tid + j * 256;
                int r = chunk >> 3, c16 = chunk & 7;
                cp_async16(sb + SW128((uint32_t)(r * 128 + c16 * 16)),
                           Bb + (size_t)r * Kb + k0 + c16 * 8);
            }
        }
        cp_commit();

        // compute tile i with fragment double-buffering over kk
        const uint32_t sa = sbase + (i % STAGES) * STAGE_BYTES;
        const uint32_t sb = sa + 16384;

#pragma unroll
        for (int mi = 0; mi < 4; mi++) {
            uint32_t addr = sa + SW128(a_row + (uint32_t)(mi * 16 * 128) + a_chk);
            ldsm_x4(afr[0][mi][0], afr[0][mi][1], afr[0][mi][2], afr[0][mi][3], addr);
        }
#pragma unroll
        for (int np = 0; np < 4; np++) {
            uint32_t addr = sb + SW128(b_row + (uint32_t)(np * 16 * 128) + b_chk);
            uint32_t r0, r1, r2, r3;
            ldsm_x4(r0, r1, r2, r3, addr);
            bfr[0][np * 2 + 0][0] = r0; bfr[0][np * 2 + 0][1] = r1;
            bfr[0][np * 2 + 1][0] = r2; bfr[0][np * 2 + 1][1] = r3;
        }

#pragma unroll
        for (int kk = 0; kk < 4; kk++) {
            const int cur = kk & 1, nxt = cur ^ 1;
            if (kk < 3) {
#pragma unroll
                for (int mi = 0; mi < 4; mi++) {
                    uint32_t addr = sa + SW128(a_row + (uint32_t)(mi * 16 * 128) +
                                               (uint32_t)((kk + 1) * 32) + a_chk);
                    ldsm_x4(afr[nxt][mi][0], afr[nxt][mi][1], afr[nxt][mi][2], afr[nxt][mi][3], addr);
                }
#pragma unroll
                for (int np = 0; np < 4; np++) {
                    uint32_t addr = sb + SW128(b_row + (uint32_t)(np * 16 * 128) +
                                               (uint32_t)((kk + 1) * 32) + b_chk);
                    uint32_t r0, r1, r2, r3;
                    ldsm_x4(r0, r1, r2, r3, addr);
                    bfr[nxt][np * 2 + 0][0] = r0; bfr[nxt][np * 2 + 0][1] = r1;
                    bfr[nxt][np * 2 + 1][0] = r2; bfr[nxt][np * 2 + 1][1] = r3;
                }
            }
#pragma unroll
            for (int mi = 0; mi < 4; mi++)
#pragma unroll
                for (int ni = 0; ni < 8; ni++)
                    mma_bf16(acc[mi][ni][0], acc[mi][ni][1], acc[mi][ni][2], acc[mi][ni][3],
                             afr[cur][mi][0], afr[cur][mi][1], afr[cur][mi][2], afr[cur][mi][3],
                             bfr[cur][ni][0], bfr[cur][ni][1]);
        }
    }

    // -------- epilogue --------
    const int col_off = warp_n * 64 + (lane & 3) * 2;
    const int row_base = m0 + warp_m * 64 + (lane >> 2);

#pragma unroll
    for (int mi = 0; mi < 4; mi++) {
        const int r0 = row_base + mi * 16;
        const int r1 = r0 + 8;
        if (MODE == 2) {
            const int region = n0 >> 10;
            const int nc0 = (n0 & 1023) + col_off;
#pragma unroll
            for (int ni = 0; ni < 8; ni++) {
                const int c = nc0 + ni * 8;
                float v00 = acc[mi][ni][0], v01 = acc[mi][ni][1];
                float v10 = acc[mi][ni][2], v11 = acc[mi][ni][3];
                if (region == 2) {
                    *reinterpret_cast<float2*>(vbuf + (size_t)r0 * DMODEL + c) = make_float2(v00, v01);
                    *reinterpret_cast<float2*>(vbuf + (size_t)r1 * DMODEL + c) = make_float2(v10, v11);
                } else {
                    uint32_t hi0 = pack_bf16x2(v00, v01);
                    uint32_t hi1 = pack_bf16x2(v10, v11);
                    __nv_bfloat162 h0 = *reinterpret_cast<__nv_bfloat162*>(&hi0);
                    __nv_bfloat162 h1 = *reinterpret_cast<__nv_bfloat162*>(&hi1);
                    uint32_t lo0 = pack_bf16x2(v00 - __bfloat162float(h0.x),
                                               v01 - __bfloat162float(h0.y));
                    uint32_t lo1 = pack_bf16x2(v10 - __bfloat162float(h1.x),
                                               v11 - __bfloat162float(h1.y));
                    __nv_bfloat16* dst = (region == 0) ? q3 : k3;
                    uint32_t m0w = hi0, m1w = hi1;
                    uint32_t a0w = (region == 0) ? hi0 : lo0;
                    uint32_t a1w = (region == 0) ? hi1 : lo1;
                    uint32_t b0w = (region == 0) ? lo0 : hi0;
                    uint32_t b1w = (region == 0) ? lo1 : hi1;
                    __nv_bfloat16* p0 = dst + (size_t)r0 * (3 * DMODEL) + c;
                    __nv_bfloat16* p1 = dst + (size_t)r1 * (3 * DMODEL) + c;
                    *reinterpret_cast<uint32_t*>(p0)            = m0w;
                    *reinterpret_cast<uint32_t*>(p0 + DMODEL)   = a0w;
                    *reinterpret_cast<uint32_t*>(p0 + 2*DMODEL) = b0w;
                    *reinterpret_cast<uint32_t*>(p1)            = m1w;
                    *reinterpret_cast<uint32_t*>(p1 + DMODEL)   = a1w;
                    *reinterpret_cast<uint32_t*>(p1 + 2*DMODEL) = b1w;
                }
            }
        } else {
            float sc0, sc1;
            if (MODE == 1) { sc0 = 1.0f / rowsum[r0]; sc1 = 1.0f / rowsum[r1]; }
            else           { sc0 = alpha; sc1 = alpha; }
            float* C0 = C + (size_t)r0 * ldc + n0;
            float* C1 = C + (size_t)r1 * ldc + n0;
#pragma unroll
            for (int ni = 0; ni < 8; ni++) {
                const int c = col_off + ni * 8;
                *reinterpret_cast<float2*>(C0 + c) =
                    make_float2(acc[mi][ni][0] * sc0, acc[mi][ni][1] * sc0);
                *reinterpret_cast<float2*>(C1 + c) =
                    make_float2(acc[mi][ni][2] * sc1, acc[mi][ni][3] * sc1);
            }
        }
    }
}

// ---------------------------------------------------------------------------
// Split-convert: in fp32 [R, C] (leading dim ld) -> out bf16 [R, 3C]
// patB==0: [hi | hi | lo]   patB==1: [hi | lo | hi]
// ---------------------------------------------------------------------------
__global__ __launch_bounds__(256) void convert_split(
    const float* __restrict__ in, int ld, int R, int C,
    __nv_bfloat16* __restrict__ out, int patB)
{
    size_t idx = ((size_t)blockIdx.x * 256 + threadIdx.x) * 4;
    size_t total = (size_t)R * C;
    if (idx >= total) return;
    int r = (int)(idx / C);
    int c = (int)(idx % C);
    float4 v = *reinterpret_cast<const float4*>(in + (size_t)r * ld + c);
    float vv[4] = {v.x, v.y, v.z, v.w};
    __nv_bfloat16 hi[4], lo[4];
#pragma unroll
    for (int i = 0; i < 4; i++) {
        hi[i] = __float2bfloat16(vv[i]);
        lo[i] = __float2bfloat16(vv[i] - __bfloat162float(hi[i]));
    }
    size_t ob = (size_t)r * 3 * C + c;
    __nv_bfloat16* o0 = out + ob;
    __nv_bfloat16* o1 = out + ob + C;
    __nv_bfloat16* o2 = out + ob + 2 * C;
#pragma unroll
    for (int i = 0; i < 4; i++) {
        o0[i] = hi[i];
        o1[i] = patB ? lo[i] : hi[i];
        o2[i] = patB ? hi[i] : lo[i];
    }
}

// ---------------------------------------------------------------------------
// Transpose + split-convert for V: in fp32 [4096(K), 1024(N)] (ld=1024) ->
// out bf16 [1024, 12288] = [vh | vl | vh] along cols.
// ---------------------------------------------------------------------------
__global__ __launch_bounds__(256) void transpose_split_v(
    const float* __restrict__ in, __nv_bfloat16* __restrict__ out)
{
    __shared__ float tile[32][33];
    int n0 = blockIdx.x * 32;
    int k0 = blockIdx.y * 32;
    int tx = threadIdx.x & 31;
    int ty = threadIdx.x >> 5;
#pragma unroll
    for (int l = 0; l < 4; l++)
        tile[ty + 8 * l][tx] = in[(size_t)(k0 + ty + 8 * l) * DMODEL + n0 + tx];
    __syncthreads();
#pragma unroll
    for (int l = 0; l < 4; l++) {
        int n = n0 + ty + 8 * l;
        float v = tile[tx][ty + 8 * l];
        __nv_bfloat16 hi = __float2bfloat16(v);
        __nv_bfloat16 lo = __float2bfloat16(v - __bfloat162float(hi));
        size_t ob = (size_t)n * (3 * N_TOK) + k0 + tx;
        out[ob] = hi;
        out[ob + N_TOK] = lo;
        out[ob + 2 * N_TOK] = hi;
    }
}

// ---------------------------------------------------------------------------
// Fused softmax + P split: reads s[row], computes exp(s-max) in registers,
// writes p3 = [hi | hi | lo] bf16 directly, and rowsum.
// ---------------------------------------------------------------------------
__global__ __launch_bounds__(256) void softmax_p3(
    const float* __restrict__ S, __nv_bfloat16* __restrict__ P3,
    float* __restrict__ rowsum)
{
    __shared__ float red[256];
    const int row = blockIdx.x;
    const int tid = threadIdx.x;
    const float* s = S + (size_t)row * N_TOK;

    float4 v[4];
    float m = -INFINITY;
#pragma unroll
    for (int j = 0; j < 4; j++) {
        v[j] = *reinterpret_cast<const float4*>(s + tid * 4 + j * 1024);
        m = fmaxf(m, fmaxf(fmaxf(v[j].x, v[j].y), fmaxf(v[j].z, v[j].w)));
    }
    red[tid] = m; __syncthreads();
    for (int o = 128; o > 0; o >>= 1) {
        if (tid < o) red[tid] = fmaxf(red[tid], red[tid + o]);
        __syncthreads();
    }
    m = red[0]; __syncthreads();

    float sum = 0.0f;
#pragma unroll
    for (int j = 0; j < 4; j++) {
        v[j].x = __expf(v[j].x - m); v[j].y = __expf(v[j].y - m);
        v[j].z = __expf(v[j].z - m); v[j].w = __expf(v[j].w - m);
        sum += v[j].x + v[j].y + v[j].z + v[j].w;
    }
    red[tid] = sum; __syncthreads();
    for (int o = 128; o > 0; o >>= 1) {
        if (tid < o) red[tid] += red[tid + o];
        __syncthreads();
    }
    if (tid == 0) rowsum[row] = red[0];

    __nv_bfloat16* p = P3 + (size_t)row * 3 * N_TOK;
#pragma unroll
    for (int j = 0; j < 4; j++) {
        const int idx = tid * 4 + j * 1024;
        float vv[4] = {v[j].x, v[j].y, v[j].z, v[j].w};
        union { __nv_bfloat16 h[4]; uint2 u; } ph, pl;
#pragma unroll
        for (int i = 0; i < 4; i++) {
            ph.h[i] = __float2bfloat16(vv[i]);
            pl.h[i] = __float2bfloat16(vv[i] - __bfloat162float(ph.h[i]));
        }
        *reinterpret_cast<uint2*>(p + idx)              = ph.u;
        *reinterpret_cast<uint2*>(p + idx + N_TOK)      = ph.u;
        *reinterpret_cast<uint2*>(p + idx + 2 * N_TOK)  = pl.u;
    }
}

// ---------------------------------------------------------------------------
extern "C" void kernel_launch(void* const* d_in, const int* in_sizes, int n_in,
                              void* d_out, int out_size)
{
    const float* x  = (const float*)d_in[0];
    const float* wq = (const float*)d_in[1];
    const float* wk = (const float*)d_in[2];
    const float* wv = (const float*)d_in[3];
    float* out = (float*)d_out;

    __nv_bfloat16 *x3, *w3, *q3, *k3, *p3, *v3t;
    float *vbuf, *s, *rs;
    cudaGetSymbolAddress((void**)&x3,   g_x3);
    cudaGetSymbolAddress((void**)&w3,   g_w3);
    cudaGetSymbolAddress((void**)&vbuf, g_vbuf);
    cudaGetSymbolAddress((void**)&q3,   g_q3);
    cudaGetSymbolAddress((void**)&k3,   g_k3);
    cudaGetSymbolAddress((void**)&s,    g_s);
    cudaGetSymbolAddress((void**)&p3,   g_p3);
    cudaGetSymbolAddress((void**)&v3t,  g_v3t);
    cudaGetSymbolAddress((void**)&rs,   g_rowsum);

    cudaFuncSetAttribute(gemm_tc<0>, cudaFuncAttributeMaxDynamicSharedMemorySize, GEMM_SMEM_BYTES);
    cudaFuncSetAttribute(gemm_tc<1>, cudaFuncAttributeMaxDynamicSharedMemorySize, GEMM_SMEM_BYTES);
    cudaFuncSetAttribute(gemm_tc<2>, cudaFuncAttributeMaxDynamicSharedMemorySize, GEMM_SMEM_BYTES);

    dim3 blk(256);
    const int CV = 256 * 4;

    // Split inputs (launches 0-3)
    convert_split<<<(N_TOK * DMODEL) / CV, blk>>>(x, DMODEL, N_TOK, DMODEL, x3, 0);
    convert_split<<<(DMODEL * DMODEL) / CV, blk>>>(wq, DMODEL, DMODEL, DMODEL, w3, 1);
    convert_split<<<(DMODEL * DMODEL) / CV, blk>>>(wk, DMODEL, DMODEL, DMODEL,
                                                   w3 + (size_t)DMODEL * 3 * DMODEL, 1);
    convert_split<<<(DMODEL * DMODEL) / CV, blk>>>(wv, DMODEL, DMODEL, DMODEL,
                                                   w3 + (size_t)2 * DMODEL * 3 * DMODEL, 1);

    // launch 4: QKV with fused split epilogue
    gemm_tc<2><<<dim3(3 * DMODEL / 256, N_TOK / 128), blk, GEMM_SMEM_BYTES>>>(
        x3, w3, nullptr, 3 * DMODEL, 0, 1.0f, nullptr, q3, k3, vbuf);

    // launch 5: scores = (q @ k^T) / 32   (positioned here so ncu -s 5 captures it)
    gemm_tc<0><<<dim3(N_TOK / 256, N_TOK / 128), blk, GEMM_SMEM_BYTES>>>(
        q3, k3, s, 3 * DMODEL, N_TOK, 1.0f / 32.0f, nullptr, nullptr, nullptr, nullptr);

    // launch 6: transpose+split v (independent of scores; needed before PV)
    transpose_split_v<<<dim3(DMODEL / 32, N_TOK / 32), blk>>>(vbuf, v3t);

    // launch 7: fused softmax + P split
    softmax_p3<<<N_TOK, blk>>>(s, p3, rs);

    // launch 8: out = (P @ v) / rowsum
    gemm_tc<1><<<dim3(DMODEL / 256, N_TOK / 128), blk, GEMM_SMEM_BYTES>>>(
        p3, v3t, out, 3 * N_TOK, DMODEL, 1.0f, rs, nullptr, nullptr, nullptr);
}